// round 6
// baseline (speedup 1.0000x reference)
#include <cuda_runtime.h>
#include <cuda_fp16.h>

#define BATCH 64
#define CH    512
#define TT    784      // 28*28
#define HID   512
#define NC    30
#define LR    8
#define STEPS 501
#define XW    542      // CH + NC
#define NBLK  148
#define GW    (NBLK * 16)   // total warps in persistent grid

// ---------------- scratch (static device globals; no allocation) ----------------
__device__ __half g_feat16[BATCH * CH * TT];          // [b][c][t]  51.4 MB
__device__ __half g_fproj16[BATCH * TT * HID];        // [b][t][h]  51.4 MB
__device__ float  g_wihx[3 * HID * CH];               // repacked x-part of gru_w_ih
__device__ float  g_hiddenA[BATCH * HID];
__device__ float  g_hiddenB[BATCH * HID];
__device__ float  g_hproj[BATCH * HID];
__device__ float  g_s[BATCH * TT];                    // exp(e)
__device__ float  g_denom[BATCH];
__device__ float  g_ctx[BATCH * CH];                  // unnormalized context
__device__ float  g_gi[3 * HID * BATCH];              // W_ih·ctx   [row][b]
__device__ float  g_gh[3 * HID * BATCH];              // W_hh·hid   [row][b]
__device__ float  g_s1[BATCH * HID];
__device__ float  g_l1[BATCH * HID];
__device__ int    g_chars[BATCH];
__device__ unsigned g_bar_count;
__device__ unsigned g_bar_gen;

// ---------------- helpers ----------------
__device__ __forceinline__ float tanha(float x) {
    float y; asm("tanh.approx.f32 %0, %1;" : "=f"(y) : "f"(x)); return y;
}
__device__ __forceinline__ float wred(float v) {
#pragma unroll
    for (int o = 16; o; o >>= 1) v += __shfl_xor_sync(0xffffffffu, v, o);
    return v;
}
__device__ __forceinline__ float sigm(float x) { return 1.f / (1.f + __expf(-x)); }

// Grid-wide barrier (all NBLK blocks resident: 1 block/SM).
// __threadfence() on sm_103a emits CCTL.IVALL -> flushes this SM's L1D, giving
// release/acquire + L1 coherence across SMs (same pattern as cg::grid.sync()).
__device__ __forceinline__ void gridbar() {
    __syncthreads();
    if (threadIdx.x == 0) {
        __threadfence();                                   // release (cumulative)
        unsigned gen = *(volatile unsigned*)&g_bar_gen;
        if (atomicAdd(&g_bar_count, 1u) == NBLK - 1) {
            g_bar_count = 0;
            __threadfence();
            *(volatile unsigned*)&g_bar_gen = gen + 1;
        } else {
            while (*(volatile unsigned*)&g_bar_gen == gen) {}
        }
        __threadfence();                                   // acquire (L1 invalidate)
    }
    __syncthreads();
}

// ---------------- setup: fp16 convert + weight repack + state init ----------------
__global__ void k_setup(const float* __restrict__ fea, const float* __restrict__ wih,
                        const float* __restrict__ h2hb) {
    const int n = BATCH * CH * TT;
    for (int i = blockIdx.x * blockDim.x + threadIdx.x; i < n; i += gridDim.x * blockDim.x) {
        g_feat16[i] = __float2half_rn(fea[i]);
        if (i < 3 * HID * CH) {
            int r = i / CH, c = i % CH;
            g_wihx[i] = wih[r * XW + c];
        }
        if (i < BATCH * HID) {
            g_hiddenA[i] = 0.f;
            g_hproj[i]   = h2hb[i % HID];   // hidden0 = 0 -> hproj = bias
        }
        if (i < BATCH) g_chars[i] = 0;
    }
}

// ---------------- feat_proj GEMM: out[b,t,h] = sum_c fea[b,c,t] * i2h[h,c] ----------------
__global__ __launch_bounds__(256) void k_gemm_fproj(const float* __restrict__ fea,
                                                    const float* __restrict__ w) {
    const int b  = blockIdx.z;
    const int t0 = blockIdx.x * 64;
    const int h0 = blockIdx.y * 64;
    __shared__ float As[16][64];
    __shared__ float Ws[16][68];
    const int tid = threadIdx.x;
    const int tx = tid & 15, ty = tid >> 4;
    float acc[4][4] = {};
    const float* feaB = fea + (size_t)b * CH * TT;

    for (int c0 = 0; c0 < CH; c0 += 16) {
        int tcol = tid & 63, crow = tid >> 6;
#pragma unroll
        for (int i = 0; i < 4; i++) {
            int c = crow + 4 * i;
            int t = t0 + tcol;
            As[c][tcol] = (t < TT) ? feaB[(c0 + c) * TT + t] : 0.f;
        }
        int cc = tid & 15, hh0 = tid >> 4;
#pragma unroll
        for (int i = 0; i < 4; i++) {
            int hh = hh0 + 16 * i;
            Ws[cc][hh] = w[(h0 + hh) * CH + c0 + cc];
        }
        __syncthreads();
#pragma unroll
        for (int k = 0; k < 16; k++) {
            float a[4], bb[4];
#pragma unroll
            for (int i = 0; i < 4; i++) a[i]  = As[k][ty * 4 + i];
#pragma unroll
            for (int j = 0; j < 4; j++) bb[j] = Ws[k][tx * 4 + j];
#pragma unroll
            for (int i = 0; i < 4; i++)
#pragma unroll
                for (int j = 0; j < 4; j++) acc[i][j] += a[i] * bb[j];
        }
        __syncthreads();
    }
#pragma unroll
    for (int i = 0; i < 4; i++) {
        int t = t0 + ty * 4 + i;
        if (t < TT) {
            size_t base = ((size_t)b * TT + t) * HID + h0 + tx * 4;
#pragma unroll
            for (int j = 0; j < 4; j++) g_fproj16[base + j] = __float2half_rn(acc[i][j]);
        }
    }
}

// ---------------- heads (logits + argmax + softmax/sigmoid outputs), 512-thread block ----------------
__device__ void do_head(int b, int step, const float* __restrict__ sg2w,
                        const float* __restrict__ sg2b, const float* __restrict__ lg2w,
                        const float* __restrict__ lg2b, float* __restrict__ out) {
    __shared__ float sl[NC + LR];
    const int warp = threadIdx.x >> 5, lane = threadIdx.x & 31;
    for (int o = warp; o < NC + LR; o += 16) {
        const float* vec; const float* wr; float bias;
        if (o < NC) { vec = g_s1 + b * HID; wr = sg2w + o * HID;        bias = sg2b[o]; }
        else        { vec = g_l1 + b * HID; wr = lg2w + (o - NC) * HID; bias = lg2b[o - NC]; }
        float acc = 0.f;
        for (int c = lane; c < HID; c += 32) acc += vec[c] * wr[c];
        acc = wred(acc);
        if (lane == 0) sl[o] = acc + bias;
    }
    __syncthreads();
    if (warp == 0) {
        float v = (lane < NC) ? sl[lane] : -1e30f;
        float m = v;
#pragma unroll
        for (int o = 16; o; o >>= 1) m = fmaxf(m, __shfl_xor_sync(0xffffffffu, m, o));
        unsigned bal = __ballot_sync(0xffffffffu, v == m);
        int idx = __ffs(bal) - 1;                       // first max -> jnp.argmax semantics
        if (lane == 0) g_chars[b] = idx;
        float e = (lane < NC) ? __expf(v - m) : 0.f;
        float ssum = wred(e);
        if (lane < NC)
            out[((size_t)b * STEPS + step) * NC + lane] = e / ssum;
        if (lane < LR)
            out[(size_t)BATCH * STEPS * NC + ((size_t)b * STEPS + step) * LR + lane] =
                1.f / (1.f + __expf(-sl[NC + lane]));
    }
}

// ---------------- persistent decode loop ----------------
__global__ __launch_bounds__(512, 1) void k_loop(
    const float* __restrict__ score_w,
    const float* __restrict__ wih_full, const float* __restrict__ whh,
    const float* __restrict__ bih,      const float* __restrict__ bhh,
    const float* __restrict__ sg1w, const float* __restrict__ sg1b,
    const float* __restrict__ sg2w, const float* __restrict__ sg2b,
    const float* __restrict__ lg1w, const float* __restrict__ lg1b,
    const float* __restrict__ lg2w, const float* __restrict__ lg2b,
    const float* __restrict__ h2hw, const float* __restrict__ h2hb,
    float* __restrict__ out)
{
    const int bi = blockIdx.x;
    const int tid = threadIdx.x;
    const int warp = tid >> 5, lane = tid & 31;
    const int gwarp = bi * 16 + warp;
    __shared__ float s_srow[TT];

    for (int s = 0; s < STEPS; s++) {
        const float* hin  = (s & 1) ? g_hiddenB : g_hiddenA;
        float*       hout = (s & 1) ? g_hiddenA : g_hiddenB;

        // ===== Phase 1: attention scores (exp(e)) + previous-step heads =====
        for (int task = gwarp; task < 6272; task += GW) {       // 64 b * 98 t-chunks
            const int b = task / 98, tchunk = task % 98;
            float sv[16], hp[16];
            const float* svp = score_w + lane * 16;
            const float* hpp = g_hproj + b * HID + lane * 16;
#pragma unroll
            for (int i = 0; i < 16; i++) { sv[i] = svp[i]; hp[i] = hpp[i]; }
#pragma unroll
            for (int tt = 0; tt < 8; tt++) {
                int t = tchunk * 8 + tt;
                const __half* fp = g_fproj16 + ((size_t)b * TT + t) * HID + lane * 16;
                uint4 u0 = *(const uint4*)(fp);
                uint4 u1 = *(const uint4*)(fp + 8);
                const __half2* h2a = (const __half2*)&u0;
                const __half2* h2b = (const __half2*)&u1;
                float acc = 0.f;
#pragma unroll
                for (int i = 0; i < 4; i++) {
                    float2 f = __half22float2(h2a[i]);
                    acc += sv[2 * i]     * tanha(f.x + hp[2 * i]);
                    acc += sv[2 * i + 1] * tanha(f.y + hp[2 * i + 1]);
                }
#pragma unroll
                for (int i = 0; i < 4; i++) {
                    float2 f = __half22float2(h2b[i]);
                    acc += sv[8 + 2 * i]     * tanha(f.x + hp[8 + 2 * i]);
                    acc += sv[8 + 2 * i + 1] * tanha(f.y + hp[8 + 2 * i + 1]);
                }
                acc = wred(acc);
                if (lane == 0) g_s[b * TT + t] = __expf(acc);
            }
        }
        if (s > 0 && bi < BATCH) do_head(bi, s - 1, sg2w, sg2b, lg2w, lg2b, out);
        gridbar();

        // ===== Phase 2: context (smem-staged score row) + denom =====
        for (int bt = bi; bt < 512; bt += NBLK) {               // (b, c-group of 64)
            const int b = bt >> 3, cg = bt & 7;
            __syncthreads();
            for (int i = tid; i < TT; i += 512) s_srow[i] = g_s[b * TT + i];
            __syncthreads();
#pragma unroll
            for (int q = 0; q < 4; q++) {
                const int c = cg * 64 + warp * 4 + q;
                const __half* fp = g_feat16 + ((size_t)b * CH + c) * TT;
                float acc = 0.f;
                for (int j = lane; j < 98; j += 32) {
                    int t = j * 8;
                    uint4 u = *(const uint4*)(fp + t);
                    const __half2* h2 = (const __half2*)&u;
                    float2 f;
                    f = __half22float2(h2[0]); acc += f.x * s_srow[t]     + f.y * s_srow[t + 1];
                    f = __half22float2(h2[1]); acc += f.x * s_srow[t + 2] + f.y * s_srow[t + 3];
                    f = __half22float2(h2[2]); acc += f.x * s_srow[t + 4] + f.y * s_srow[t + 5];
                    f = __half22float2(h2[3]); acc += f.x * s_srow[t + 6] + f.y * s_srow[t + 7];
                }
                acc = wred(acc);
                if (lane == 0) g_ctx[b * CH + c] = acc;
            }
            if (cg == 0 && warp == 0) {
                float a = 0.f;
                for (int t = lane; t < TT; t += 32) a += s_srow[t];
                a = wred(a);
                if (lane == 0) g_denom[b] = a;
            }
        }
        gridbar();

        // ===== Phase 3a: GRU matvecs, weight row in registers, 32 batches/task =====
        for (int task = gwarp; task < 3072; task += GW) {       // 1536 rows * 2 batch halves
            const int r = task >> 1;
            const int b0 = (task & 1) << 5;
            const float4* wi4 = (const float4*)(g_wihx + r * CH);
            const float4* wh4 = (const float4*)(whh + r * HID);
            float4 wi[4], wh[4];
#pragma unroll
            for (int j = 0; j < 4; j++) { wi[j] = wi4[lane + 32 * j]; wh[j] = wh4[lane + 32 * j]; }
            for (int b = b0; b < b0 + 32; b++) {
                const float4* cx = (const float4*)(g_ctx + b * CH);
                const float4* hx = (const float4*)(hin + b * HID);
                float ai = 0.f, ah = 0.f;
#pragma unroll
                for (int j = 0; j < 4; j++) {
                    float4 c = cx[lane + 32 * j], h4 = hx[lane + 32 * j];
                    ai += wi[j].x * c.x  + wi[j].y * c.y  + wi[j].z * c.z  + wi[j].w * c.w;
                    ah += wh[j].x * h4.x + wh[j].y * h4.y + wh[j].z * h4.z + wh[j].w * h4.w;
                }
                ai = wred(ai); ah = wred(ah);
                if (lane == 0) { g_gi[r * BATCH + b] = ai; g_gh[r * BATCH + b] = ah; }
            }
        }
        gridbar();

        // ===== Phase 3b: gate combine (normalization + onehot column folded in) =====
        {
            const int tg = bi * 512 + tid;                      // 0..75775
            if (tg < BATCH * HID) {
                const int b = tg & 63, h = tg >> 6;
                const float scale = 1.f / g_denom[b];
                const int ch = g_chars[b];
                float air = g_gi[h * BATCH + b]              * scale
                          + wih_full[h * XW + CH + ch]              + bih[h];
                float aiz = g_gi[(HID + h) * BATCH + b]      * scale
                          + wih_full[(HID + h) * XW + CH + ch]      + bih[HID + h];
                float ain = g_gi[(2 * HID + h) * BATCH + b]  * scale
                          + wih_full[(2 * HID + h) * XW + CH + ch]  + bih[2 * HID + h];
                float ahr = g_gh[h * BATCH + b]             + bhh[h];
                float ahz = g_gh[(HID + h) * BATCH + b]     + bhh[HID + h];
                float ahn = g_gh[(2 * HID + h) * BATCH + b] + bhh[2 * HID + h];
                float r = sigm(air + ahr);
                float z = sigm(aiz + ahz);
                float n = tanhf(ain + r * ahn);
                hout[b * HID + h] = (1.f - z) * n + z * hin[b * HID + h];
            }
        }
        gridbar();

        // ===== Phase 4: post projections (s1, l1, next hproj), rows in registers =====
        for (int task = gwarp; task < 3072; task += GW) {       // 1536 rows * 2 halves
            const int r = task >> 1;
            const int b0 = (task & 1) << 5;
            const int m = r >> 9, h = r & 511;
            const float* wrow = (m == 0 ? sg1w : m == 1 ? lg1w : h2hw) + h * HID;
            const float bias  = (m == 0 ? sg1b[h] : m == 1 ? lg1b[h] : h2hb[h]);
            float* dst        = (m == 0 ? g_s1 : m == 1 ? g_l1 : g_hproj);
            const float4* w4 = (const float4*)wrow;
            float4 w[4];
#pragma unroll
            for (int j = 0; j < 4; j++) w[j] = w4[lane + 32 * j];
            for (int b = b0; b < b0 + 32; b++) {
                const float4* hx = (const float4*)(hout + b * HID);
                float a = 0.f;
#pragma unroll
                for (int j = 0; j < 4; j++) {
                    float4 h4 = hx[lane + 32 * j];
                    a += w[j].x * h4.x + w[j].y * h4.y + w[j].z * h4.z + w[j].w * h4.w;
                }
                a = wred(a);
                if (lane == 0) dst[b * HID + h] = a + bias;
            }
        }
        gridbar();
    }

    // ===== final-step heads =====
    if (bi < BATCH) do_head(bi, STEPS - 1, sg2w, sg2b, lg2w, lg2b, out);
}

// ---------------- launch ----------------
extern "C" void kernel_launch(void* const* d_in, const int* in_sizes, int n_in,
                              void* d_out, int out_size) {
    const float* fea     = (const float*)d_in[0];
    const float* i2h_w   = (const float*)d_in[1];
    const float* h2h_w   = (const float*)d_in[2];
    const float* h2h_b   = (const float*)d_in[3];
    const float* score_w = (const float*)d_in[4];
    const float* gw_ih   = (const float*)d_in[5];
    const float* gw_hh   = (const float*)d_in[6];
    const float* gb_ih   = (const float*)d_in[7];
    const float* gb_hh   = (const float*)d_in[8];
    const float* sg1w    = (const float*)d_in[9];
    const float* sg1b    = (const float*)d_in[10];
    const float* sg2w    = (const float*)d_in[11];
    const float* sg2b    = (const float*)d_in[12];
    const float* lg1w    = (const float*)d_in[13];
    const float* lg1b    = (const float*)d_in[14];
    const float* lg2w    = (const float*)d_in[15];
    const float* lg2b    = (const float*)d_in[16];
    float* out = (float*)d_out;

    k_setup<<<4096, 256>>>(fea, gw_ih, h2h_b);
    k_gemm_fproj<<<dim3(13, 8, 64), 256>>>(fea, i2h_w);
    k_loop<<<NBLK, 512>>>(score_w, gw_ih, gw_hh, gb_ih, gb_hh,
                          sg1w, sg1b, sg2w, sg2b,
                          lg1w, lg1b, lg2w, lg2b,
                          h2h_w, h2h_b, out);
}

// round 11
// speedup vs baseline: 1.3019x; 1.3019x over previous
#include <cuda_runtime.h>
#include <cuda_fp16.h>

#define BATCH 64
#define CH    512
#define TT    784      // 28*28
#define HID   512
#define NC    30
#define LR    8
#define STEPS 501
#define XW    542      // CH + NC
#define NBLK  148
#define GW    (NBLK * 16)   // total warps in persistent grid

// ---------------- scratch (static device globals; no allocation) ----------------
// __align__(16): these are accessed through float4/uint4 casts; device globals
// otherwise only guarantee element-type alignment.
__device__ __align__(16) __half g_feat16[BATCH * CH * TT];    // [b][c][t]  51.4 MB
__device__ __align__(16) __half g_fproj16[BATCH * TT * HID];  // [b][t][h]  51.4 MB
__device__ __align__(16) float  g_wihx[3 * HID * CH];         // repacked x-part of gru_w_ih
__device__ __align__(16) float  g_hiddenA[BATCH * HID];
__device__ __align__(16) float  g_hiddenB[BATCH * HID];
__device__ __align__(16) float  g_hproj[BATCH * HID];
__device__ __align__(16) float  g_s[BATCH * TT];              // exp(e)
__device__ __align__(16) float  g_denom[BATCH];
__device__ __align__(16) float  g_ctx[BATCH * CH];            // unnormalized context
__device__ __align__(16) float  g_gi[3 * HID * BATCH];        // W_ih·ctx   [row][b]
__device__ __align__(16) float  g_gh[3 * HID * BATCH];        // W_hh·hid   [row][b]
__device__ __align__(16) float  g_s1[BATCH * HID];
__device__ __align__(16) float  g_l1[BATCH * HID];
__device__ int    g_chars[BATCH];
__device__ unsigned g_bar_count;
__device__ unsigned g_bar_gen;

// ---------------- helpers ----------------
__device__ __forceinline__ float tanha(float x) {
    float y; asm("tanh.approx.f32 %0, %1;" : "=f"(y) : "f"(x)); return y;
}
__device__ __forceinline__ float wred(float v) {
#pragma unroll
    for (int o = 16; o; o >>= 1) v += __shfl_xor_sync(0xffffffffu, v, o);
    return v;
}
__device__ __forceinline__ float sigm(float x) { return 1.f / (1.f + __expf(-x)); }
__device__ __forceinline__ float dot4(float4 a, float4 b) {
    return a.x * b.x + a.y * b.y + a.z * b.z + a.w * b.w;
}

// Grid-wide barrier (all NBLK blocks resident: 1 block/SM).
__device__ __forceinline__ void gridbar() {
    __syncthreads();
    if (threadIdx.x == 0) {
        __threadfence();                                   // release
        unsigned gen = *(volatile unsigned*)&g_bar_gen;
        if (atomicAdd(&g_bar_count, 1u) == NBLK - 1) {
            g_bar_count = 0;
            __threadfence();
            *(volatile unsigned*)&g_bar_gen = gen + 1;
        } else {
            while (*(volatile unsigned*)&g_bar_gen == gen) {}
        }
        __threadfence();                                   // acquire (L1 invalidate)
    }
    __syncthreads();
}

// ---------------- setup: fp16 convert + weight repack + state init ----------------
__global__ void k_setup(const float* __restrict__ fea, const float* __restrict__ wih,
                        const float* __restrict__ h2hb) {
    const int n = BATCH * CH * TT;
    for (int i = blockIdx.x * blockDim.x + threadIdx.x; i < n; i += gridDim.x * blockDim.x) {
        g_feat16[i] = __float2half_rn(fea[i]);
        if (i < 3 * HID * CH) {
            int r = i / CH, c = i % CH;
            g_wihx[i] = wih[r * XW + c];
        }
        if (i < BATCH * HID) {
            g_hiddenA[i] = 0.f;
            g_hproj[i]   = h2hb[i % HID];   // hidden0 = 0 -> hproj = bias
        }
        if (i < BATCH) g_chars[i] = 0;
    }
}

// ---------------- feat_proj GEMM: out[b,t,h] = sum_c fea[b,c,t] * i2h[h,c] ----------------
__global__ __launch_bounds__(256) void k_gemm_fproj(const float* __restrict__ fea,
                                                    const float* __restrict__ w) {
    const int b  = blockIdx.z;
    const int t0 = blockIdx.x * 64;
    const int h0 = blockIdx.y * 64;
    __shared__ __align__(16) float As[16][64];
    __shared__ __align__(16) float Ws[16][68];
    const int tid = threadIdx.x;
    const int tx = tid & 15, ty = tid >> 4;
    float acc[4][4] = {};
    const float* feaB = fea + (size_t)b * CH * TT;

    for (int c0 = 0; c0 < CH; c0 += 16) {
        int tcol = tid & 63, crow = tid >> 6;
#pragma unroll
        for (int i = 0; i < 4; i++) {
            int c = crow + 4 * i;
            int t = t0 + tcol;
            As[c][tcol] = (t < TT) ? feaB[(c0 + c) * TT + t] : 0.f;
        }
        int cc = tid & 15, hh0 = tid >> 4;
#pragma unroll
        for (int i = 0; i < 4; i++) {
            int hh = hh0 + 16 * i;
            Ws[cc][hh] = w[(h0 + hh) * CH + c0 + cc];
        }
        __syncthreads();
#pragma unroll
        for (int k = 0; k < 16; k++) {
            float a[4], bb[4];
#pragma unroll
            for (int i = 0; i < 4; i++) a[i]  = As[k][ty * 4 + i];
#pragma unroll
            for (int j = 0; j < 4; j++) bb[j] = Ws[k][tx * 4 + j];
#pragma unroll
            for (int i = 0; i < 4; i++)
#pragma unroll
                for (int j = 0; j < 4; j++) acc[i][j] += a[i] * bb[j];
        }
        __syncthreads();
    }
#pragma unroll
    for (int i = 0; i < 4; i++) {
        int t = t0 + ty * 4 + i;
        if (t < TT) {
            size_t base = ((size_t)b * TT + t) * HID + h0 + tx * 4;
#pragma unroll
            for (int j = 0; j < 4; j++) g_fproj16[base + j] = __float2half_rn(acc[i][j]);
        }
    }
}

// ---------------- heads (logits + argmax + softmax/sigmoid outputs), 512-thread block ----------------
__device__ void do_head(int b, int step, const float* __restrict__ sg2w,
                        const float* __restrict__ sg2b, const float* __restrict__ lg2w,
                        const float* __restrict__ lg2b, float* __restrict__ out) {
    __shared__ __align__(16) float sl[NC + LR + 2];   // padded to 16B multiple
    const int warp = threadIdx.x >> 5, lane = threadIdx.x & 31;
    for (int o = warp; o < NC + LR; o += 16) {
        const float* vec; const float* wr; float bias;
        if (o < NC) { vec = g_s1 + b * HID; wr = sg2w + o * HID;        bias = sg2b[o]; }
        else        { vec = g_l1 + b * HID; wr = lg2w + (o - NC) * HID; bias = lg2b[o - NC]; }
        float acc = 0.f;
        for (int c = lane; c < HID; c += 32) acc += vec[c] * wr[c];
        acc = wred(acc);
        if (lane == 0) sl[o] = acc + bias;
    }
    __syncthreads();
    if (warp == 0) {
        float v = (lane < NC) ? sl[lane] : -1e30f;
        float m = v;
#pragma unroll
        for (int o = 16; o; o >>= 1) m = fmaxf(m, __shfl_xor_sync(0xffffffffu, m, o));
        unsigned bal = __ballot_sync(0xffffffffu, v == m);
        int idx = __ffs(bal) - 1;                       // first max -> jnp.argmax semantics
        if (lane == 0) g_chars[b] = idx;
        float e = (lane < NC) ? __expf(v - m) : 0.f;
        float ssum = wred(e);
        if (lane < NC)
            out[((size_t)b * STEPS + step) * NC + lane] = e / ssum;
        if (lane < LR)
            out[(size_t)BATCH * STEPS * NC + ((size_t)b * STEPS + step) * LR + lane] =
                1.f / (1.f + __expf(-sl[NC + lane]));
    }
}

// ---------------- persistent decode loop ----------------
__global__ __launch_bounds__(512, 1) void k_loop(
    const float* __restrict__ score_w,
    const float* __restrict__ wih_full, const float* __restrict__ whh,
    const float* __restrict__ bih,      const float* __restrict__ bhh,
    const float* __restrict__ sg1w, const float* __restrict__ sg1b,
    const float* __restrict__ sg2w, const float* __restrict__ sg2b,
    const float* __restrict__ lg1w, const float* __restrict__ lg1b,
    const float* __restrict__ lg2w, const float* __restrict__ lg2b,
    const float* __restrict__ h2hw, const float* __restrict__ h2hb,
    float* __restrict__ out)
{
    const int bi = blockIdx.x;
    const int tid = threadIdx.x;
    const int warp = tid >> 5, lane = tid & 31;
    const int gwarp = bi * 16 + warp;
    __shared__ __align__(16) float s_srow[TT];
    __shared__ __align__(16) float s_X[16 * 512];      // staged activations (16 batches x 512)

    for (int s = 0; s < STEPS; s++) {
        const float* hin  = (s & 1) ? g_hiddenB : g_hiddenA;
        float*       hout = (s & 1) ? g_hiddenA : g_hiddenB;

        // ===== Phase 1: attention scores (exp(e)) + previous-step heads =====
        for (int task = gwarp; task < 6272; task += GW) {       // 64 b * 98 t-chunks
            const int b = task / 98, tchunk = task % 98;
            float sv[16], hp[16];
            const float* svp = score_w + lane * 16;
            const float* hpp = g_hproj + b * HID + lane * 16;
#pragma unroll
            for (int i = 0; i < 16; i++) { sv[i] = svp[i]; hp[i] = hpp[i]; }
#pragma unroll
            for (int tt = 0; tt < 8; tt++) {
                int t = tchunk * 8 + tt;
                const __half* fp = g_fproj16 + ((size_t)b * TT + t) * HID + lane * 16;
                uint4 u0 = *(const uint4*)(fp);
                uint4 u1 = *(const uint4*)(fp + 8);
                const __half2* h2a = (const __half2*)&u0;
                const __half2* h2b = (const __half2*)&u1;
                float acc = 0.f;
#pragma unroll
                for (int i = 0; i < 4; i++) {
                    float2 f = __half22float2(h2a[i]);
                    acc += sv[2 * i]     * tanha(f.x + hp[2 * i]);
                    acc += sv[2 * i + 1] * tanha(f.y + hp[2 * i + 1]);
                }
#pragma unroll
                for (int i = 0; i < 4; i++) {
                    float2 f = __half22float2(h2b[i]);
                    acc += sv[8 + 2 * i]     * tanha(f.x + hp[8 + 2 * i]);
                    acc += sv[8 + 2 * i + 1] * tanha(f.y + hp[8 + 2 * i + 1]);
                }
                acc = wred(acc);
                if (lane == 0) g_s[b * TT + t] = __expf(acc);
            }
        }
        if (s > 0 && bi < BATCH) do_head(bi, s - 1, sg2w, sg2b, lg2w, lg2b, out);
        gridbar();

        // ===== Phase 2: context (smem-staged score row) + denom =====
        for (int bt = bi; bt < 512; bt += NBLK) {               // (b, c-group of 64)
            const int b = bt >> 3, cg = bt & 7;
            __syncthreads();
            for (int i = tid; i < TT; i += 512) s_srow[i] = g_s[b * TT + i];
            __syncthreads();
#pragma unroll
            for (int q = 0; q < 4; q++) {
                const int c = cg * 64 + warp * 4 + q;
                const __half* fp = g_feat16 + ((size_t)b * CH + c) * TT;
                float acc = 0.f;
                for (int j = lane; j < 98; j += 32) {
                    int t = j * 8;
                    uint4 u = *(const uint4*)(fp + t);
                    const __half2* h2 = (const __half2*)&u;
                    float2 f;
                    f = __half22float2(h2[0]); acc += f.x * s_srow[t]     + f.y * s_srow[t + 1];
                    f = __half22float2(h2[1]); acc += f.x * s_srow[t + 2] + f.y * s_srow[t + 3];
                    f = __half22float2(h2[2]); acc += f.x * s_srow[t + 4] + f.y * s_srow[t + 5];
                    f = __half22float2(h2[3]); acc += f.x * s_srow[t + 6] + f.y * s_srow[t + 7];
                }
                acc = wred(acc);
                if (lane == 0) g_ctx[b * CH + c] = acc;
            }
            if (cg == 0 && warp == 0) {
                float a = 0.f;
                for (int t = lane; t < TT; t += 32) a += s_srow[t];
                a = wred(a);
                if (lane == 0) g_denom[b] = a;
            }
        }
        gridbar();

        // ===== Phase 3a: GRU matvecs as smem-staged tiles =====
        // 128 tasks: (kind gi/gh x 16 row-blocks of 96) x 4 batch-quarters
        if (bi < 128) {
            const int rowblk = bi >> 2, q = bi & 3;
            const int b0 = q * 16;
            const bool is_gh = rowblk >= 16;
            const float* X = is_gh ? hin : g_ctx;
            const float* W = is_gh ? whh : g_wihx;
            const int r0 = (is_gh ? rowblk - 16 : rowblk) * 96;
            float* dst = is_gh ? g_gh : g_gi;
            {   // stage X: 16 batches x 512 floats
                const float4* src = (const float4*)(X + b0 * 512);
                float4* d4 = (float4*)s_X;
                for (int i = tid; i < 2048; i += 512) d4[i] = src[i];
            }
            __syncthreads();
#pragma unroll
            for (int rp = 0; rp < 3; rp++) {                     // 6 rows/warp, 2 at a time
                const int r = r0 + warp * 6 + rp * 2;
                const float4* w0 = (const float4*)(W + (size_t)r * 512);
                const float4* w1 = (const float4*)(W + (size_t)(r + 1) * 512);
                float4 wa[4], wb[4];
#pragma unroll
                for (int j = 0; j < 4; j++) { wa[j] = w0[lane + 32 * j]; wb[j] = w1[lane + 32 * j]; }
#pragma unroll
                for (int bp = 0; bp < 8; bp++) {                 // 16 batches, 2 at a time
                    const float4* x0 = (const float4*)(s_X + (bp * 2)     * 512);
                    const float4* x1 = (const float4*)(s_X + (bp * 2 + 1) * 512);
                    float a00 = 0.f, a01 = 0.f, a10 = 0.f, a11 = 0.f;
#pragma unroll
                    for (int j = 0; j < 4; j++) {
                        float4 xa = x0[lane + 32 * j], xb = x1[lane + 32 * j];
                        a00 += dot4(wa[j], xa); a01 += dot4(wa[j], xb);
                        a10 += dot4(wb[j], xa); a11 += dot4(wb[j], xb);
                    }
                    a00 = wred(a00); a01 = wred(a01); a10 = wred(a10); a11 = wred(a11);
                    if (lane == 0) {
                        const int b = b0 + bp * 2;
                        dst[r * BATCH + b]           = a00;
                        dst[r * BATCH + b + 1]       = a01;
                        dst[(r + 1) * BATCH + b]     = a10;
                        dst[(r + 1) * BATCH + b + 1] = a11;
                    }
                }
            }
        }
        gridbar();

        // ===== Phase 3b: gate combine (normalization + onehot column folded in) =====
        {
            const int tg = bi * 512 + tid;                      // 0..75775
            if (tg < BATCH * HID) {
                const int b = tg & 63, h = tg >> 6;
                const float scale = 1.f / g_denom[b];
                const int ch = g_chars[b];
                float air = g_gi[h * BATCH + b]              * scale
                          + wih_full[h * XW + CH + ch]              + bih[h];
                float aiz = g_gi[(HID + h) * BATCH + b]      * scale
                          + wih_full[(HID + h) * XW + CH + ch]      + bih[HID + h];
                float ain = g_gi[(2 * HID + h) * BATCH + b]  * scale
                          + wih_full[(2 * HID + h) * XW + CH + ch]  + bih[2 * HID + h];
                float ahr = g_gh[h * BATCH + b]             + bhh[h];
                float ahz = g_gh[(HID + h) * BATCH + b]     + bhh[HID + h];
                float ahn = g_gh[(2 * HID + h) * BATCH + b] + bhh[2 * HID + h];
                float r = sigm(air + ahr);
                float z = sigm(aiz + ahz);
                float n = tanhf(ain + r * ahn);
                hout[b * HID + h] = (1.f - z) * n + z * hin[b * HID + h];
            }
        }
        gridbar();

        // ===== Phase 4: post projections (s1, l1, next hproj) as smem-staged tiles =====
        // 96 tasks: 24 row-blocks of 64 (unified 1536-row space) x 4 batch-quarters
        if (bi < 96) {
            const int rowblk = bi >> 2, q = bi & 3;
            const int b0 = q * 16;
            const int r0 = rowblk * 64;
            {   // stage hout: 16 batches x 512
                const float4* src = (const float4*)(hout + b0 * 512);
                float4* d4 = (float4*)s_X;
                for (int i = tid; i < 2048; i += 512) d4[i] = src[i];
            }
            __syncthreads();
            const int m = r0 >> 9;                               // whole block in one matrix
            const float* Wm = (m == 0 ? sg1w : m == 1 ? lg1w : h2hw);
            const float* Bm = (m == 0 ? sg1b : m == 1 ? lg1b : h2hb);
            float* dst      = (m == 0 ? g_s1 : m == 1 ? g_l1 : g_hproj);
            const int hbase = r0 & 511;
#pragma unroll
            for (int rp = 0; rp < 2; rp++) {                     // 4 rows/warp, 2 at a time
                const int h = hbase + warp * 4 + rp * 2;
                const float4* w0 = (const float4*)(Wm + (size_t)h * 512);
                const float4* w1 = (const float4*)(Wm + (size_t)(h + 1) * 512);
                float4 wa[4], wb[4];
#pragma unroll
                for (int j = 0; j < 4; j++) { wa[j] = w0[lane + 32 * j]; wb[j] = w1[lane + 32 * j]; }
#pragma unroll
                for (int bp = 0; bp < 8; bp++) {
                    const float4* x0 = (const float4*)(s_X + (bp * 2)     * 512);
                    const float4* x1 = (const float4*)(s_X + (bp * 2 + 1) * 512);
                    float a00 = 0.f, a01 = 0.f, a10 = 0.f, a11 = 0.f;
#pragma unroll
                    for (int j = 0; j < 4; j++) {
                        float4 xa = x0[lane + 32 * j], xb = x1[lane + 32 * j];
                        a00 += dot4(wa[j], xa); a01 += dot4(wa[j], xb);
                        a10 += dot4(wb[j], xa); a11 += dot4(wb[j], xb);
                    }
                    a00 = wred(a00); a01 = wred(a01); a10 = wred(a10); a11 = wred(a11);
                    if (lane == 0) {
                        const int b = b0 + bp * 2;
                        dst[b * HID + h]           = a00 + Bm[h];
                        dst[(b + 1) * HID + h]     = a01 + Bm[h];
                        dst[b * HID + h + 1]       = a10 + Bm[h + 1];
                        dst[(b + 1) * HID + h + 1] = a11 + Bm[h + 1];
                    }
                }
            }
        }
        gridbar();
    }

    // ===== final-step heads =====
    if (bi < BATCH) do_head(bi, STEPS - 1, sg2w, sg2b, lg2w, lg2b, out);
}

// ---------------- launch ----------------
extern "C" void kernel_launch(void* const* d_in, const int* in_sizes, int n_in,
                              void* d_out, int out_size) {
    const float* fea     = (const float*)d_in[0];
    const float* i2h_w   = (const float*)d_in[1];
    const float* h2h_w   = (const float*)d_in[2];
    const float* h2h_b   = (const float*)d_in[3];
    const float* score_w = (const float*)d_in[4];
    const float* gw_ih   = (const float*)d_in[5];
    const float* gw_hh   = (const float*)d_in[6];
    const float* gb_ih   = (const float*)d_in[7];
    const float* gb_hh   = (const float*)d_in[8];
    const float* sg1w    = (const float*)d_in[9];
    const float* sg1b    = (const float*)d_in[10];
    const float* sg2w    = (const float*)d_in[11];
    const float* sg2b    = (const float*)d_in[12];
    const float* lg1w    = (const float*)d_in[13];
    const float* lg1b    = (const float*)d_in[14];
    const float* lg2w    = (const float*)d_in[15];
    const float* lg2b    = (const float*)d_in[16];
    float* out = (float*)d_out;

    k_setup<<<4096, 256>>>(fea, gw_ih, h2h_b);
    k_gemm_fproj<<<dim3(13, 8, 64), 256>>>(fea, i2h_w);
    k_loop<<<NBLK, 512>>>(score_w, gw_ih, gw_hh, gb_ih, gb_hh,
                          sg1w, sg1b, sg2w, sg2b,
                          lg1w, lg1b, lg2w, lg2b,
                          h2h_w, h2h_b, out);
}